// round 11
// baseline (speedup 1.0000x reference)
#include <cuda_runtime.h>
#include <math.h>

#define BATCH 2
#define SEQ   4096
#define EMB   512
#define DQ    64
#define NC    129
#define ZCONST 3967.0f

typedef unsigned long long ull;

// ---- scratch (allocation-free: device globals) ----
__device__ float g_Q[BATCH * SEQ * DQ];
__device__ float g_K[BATCH * SEQ * DQ];
__device__ float g_Vc[BATCH * NC * DQ];
__device__ float g_part[BATCH * 64 * EMB];
__device__ float g_vtp[BATCH * 8 * DQ];
__device__ float4 g_Wp2[256 * DQ];   // [kp][d]: {wq2kp, wq2kp+1, wk2kp, wk2kp+1}

__device__ __forceinline__ void ffma2(ull& acc, ull a, ull b) {
    asm("fma.rn.f32x2 %0, %1, %2, %0;" : "+l"(acc) : "l"(a), "l"(b));
}
__device__ __forceinline__ ull pack2(float lo, float hi) {
    return ((ull)__float_as_uint(hi) << 32) | (ull)__float_as_uint(lo);
}
__device__ __forceinline__ float lo32(ull v) { return __uint_as_float((unsigned)v); }
__device__ __forceinline__ float hi32(ull v) { return __uint_as_float((unsigned)(v >> 32)); }

// ============================================================
// Kernel A (prep): 514 blocks x 128 threads. (unchanged)
// ============================================================
__global__ void __launch_bounds__(128)
prep_kernel(const float* __restrict__ x,
            const float* __restrict__ Wq, const float* __restrict__ Wk,
            const float* __restrict__ Wv, const float* __restrict__ bv) {
    const int bid = blockIdx.x, t = threadIdx.x;

    if (bid < 128) {
        const int kp = bid * 2 + (t >> 6);
        const int d  = t & 63;
        float4 w;
        w.x = Wq[(size_t)(2 * kp)     * DQ + d];
        w.y = Wq[(size_t)(2 * kp + 1) * DQ + d];
        w.z = Wk[(size_t)(2 * kp)     * DQ + d];
        w.w = Wk[(size_t)(2 * kp + 1) * DQ + d];
        g_Wp2[kp * DQ + d] = w;
    } else if (bid < 256) {
        const int i = bid - 128;
        const int b = i >> 6, ci = i & 63;
        int r0 = 129 + ci * 62;
        int r1 = r0 + 62; if (r1 > SEQ) r1 = SEQ;
        const float* xb = x + (size_t)b * SEQ * EMB;
        float4 s = make_float4(0.f, 0.f, 0.f, 0.f);
#pragma unroll 4
        for (int r = r0; r < r1; r++) {
            float4 v = *(const float4*)(xb + (size_t)r * EMB + t * 4);
            s.x += v.x; s.y += v.y; s.z += v.z; s.w += v.w;
        }
        *(float4*)(g_part + (b * 64 + ci) * EMB + t * 4) = s;
    } else {
        const int i = bid - 256;
        const int b = i / NC, r = i % NC;
        __shared__ float xsh[EMB];
        __shared__ float red[2][DQ];
        const float* xr = x + ((size_t)b * SEQ + r) * EMB;
        ((float4*)xsh)[t] = ((const float4*)xr)[t];
        __syncthreads();
        const int d = t & 63, h = t >> 6;
        float acc = 0.f;
        const int kb = h * 256;
#pragma unroll 8
        for (int k = 0; k < 256; k++)
            acc = fmaf(xsh[kb + k], Wv[(size_t)(kb + k) * DQ + d], acc);
        red[h][d] = acc;
        __syncthreads();
        if (t < DQ)
            g_Vc[(b * NC + r) * DQ + t] = red[0][t] + red[1][t] + bv[t];
    }
}

// ============================================================
// Kernel B: vtail partials per k-group: grid (8, 2), 256 threads. (unchanged)
// ============================================================
__global__ void vtail_combine_kernel(const float* __restrict__ Wv) {
    const int kg = blockIdx.x, b = blockIdx.y, t = threadIdx.x;
    __shared__ float red[4][DQ];
    __shared__ float xsum64[DQ];
    __shared__ float p2[4][DQ];
    {
        const int kk = t & 63, g = t >> 6;
        float s = 0.f;
#pragma unroll
        for (int ci = g; ci < 64; ci += 4)
            s += g_part[(b * 64 + ci) * EMB + kg * 64 + kk];
        red[g][kk] = s;
    }
    __syncthreads();
    if (t < DQ) xsum64[t] = red[0][t] + red[1][t] + red[2][t] + red[3][t];
    __syncthreads();
    {
        const int d = t & 63, g2 = t >> 6;
        float acc = 0.f;
#pragma unroll
        for (int kk = g2 * 16; kk < g2 * 16 + 16; kk++)
            acc = fmaf(xsum64[kk], Wv[(size_t)(kg * 64 + kk) * DQ + d], acc);
        p2[g2][d] = acc;
    }
    __syncthreads();
    if (t < DQ)
        g_vtp[(b * 8 + kg) * DQ + t] = p2[0][t] + p2[1][t] + p2[2][t] + p2[3][t];
}

// ============================================================
// Kernel C: Q/K projection (R7 config, unchanged).
// ============================================================
__global__ void __launch_bounds__(256, 3)
proj_qk_kernel(const float* __restrict__ x,
               const float* __restrict__ bq, const float* __restrict__ bk) {
    __shared__ ull xs2[32][64];
    const int b  = blockIdx.y;
    const int n0 = blockIdx.x * 32;
    const int t  = threadIdx.x;
    const int rg = t & 7;
    const int dg = t >> 3;

    ull qa[4][2], ka[4][2];
#pragma unroll
    for (int i = 0; i < 4; i++)
#pragma unroll
        for (int j = 0; j < 2; j++) { qa[i][j] = 0ull; ka[i][j] = 0ull; }

    const float* xb = x + ((size_t)b * SEQ + n0) * EMB;

    for (int k0 = 0; k0 < EMB; k0 += 128) {
        __syncthreads();
        for (int idx = t; idx < 32 * 32; idx += 256) {
            int r = idx >> 5, c = idx & 31;
            float4 v = *(const float4*)(xb + (size_t)r * EMB + k0 + c * 4);
            int sw = r >> 2;
            xs2[r][(2 * c) ^ sw]     = pack2(v.x, v.y);
            xs2[r][(2 * c + 1) ^ sw] = pack2(v.z, v.w);
        }
        __syncthreads();

        const int kpb = k0 >> 1;
#pragma unroll 4
        for (int kp = 0; kp < 64; kp++) {
            const ulonglong2* wrow =
                (const ulonglong2*)(g_Wp2 + (size_t)(kpb + kp) * DQ) + dg * 2;
            ulonglong2 w0 = wrow[0];
            ulonglong2 w1 = wrow[1];
            ull x2[4];
#pragma unroll
            for (int i = 0; i < 4; i++)
                x2[i] = xs2[rg * 4 + i][kp ^ rg];
#pragma unroll
            for (int i = 0; i < 4; i++) {
                ffma2(qa[i][0], x2[i], w0.x);
                ffma2(ka[i][0], x2[i], w0.y);
                ffma2(qa[i][1], x2[i], w1.x);
                ffma2(ka[i][1], x2[i], w1.y);
            }
        }
    }

#pragma unroll
    for (int j = 0; j < 2; j++) {
        int d = dg * 2 + j;
        float bqv = bq[d], bkv = bk[d];
#pragma unroll
        for (int i = 0; i < 4; i++) {
            int n = n0 + rg * 4 + i;
            g_Q[((size_t)b * SEQ + n) * DQ + d] = lo32(qa[i][j]) + hi32(qa[i][j]) + bqv;
            g_K[((size_t)b * SEQ + n) * DQ + d] = lo32(ka[i][j]) + hi32(ka[i][j]) + bkv;
        }
    }
}

// ============================================================
// Kernel D: attention core v3 — wavefront-minimized.
//  Warp grid 2x4; lane-adjacent rows/cols (bank stride 4 words ->
//  conflict-free); LDS.128 k-quads; FFMA2 math.
//  Pitches: Ks/Qs 68, Es/Vst 132 (rows 16B-aligned, stride = 4 mod 32).
//  Es overlays Ks after phase 1. smem 86.4KB -> 2 blocks/SM.
// ============================================================
#define KROWS 160
#define AP    68                 // Ks/Qs pitch (floats)
#define EP    132                // Es/Vst pitch (floats)
#define AKS   0                  // Ks 160*68 = 10880 ; Es overlay 32*132 = 4224
#define AQS   10880              // Qs 32*68 = 2176
#define AVS   13056              // Vst 64*132 = 8448
#define AZI   21504              // 32
#define AVT   21536              // 64
#define A_FLOATS 21600
#define A_BYTES (A_FLOATS * 4)

__global__ void __launch_bounds__(256, 2)
attn_kernel(float* __restrict__ out, const float* __restrict__ bv) {
    extern __shared__ float sm[];
    float* Ks  = sm + AKS;
    float* Es  = sm + AKS;       // overlay after phase 1
    float* Qs  = sm + AQS;
    float* Vst = sm + AVS;       // transposed V: Vst[d][c]
    float* Zi  = sm + AZI;
    float* Vt  = sm + AVT;

    const int b = blockIdx.y, n0 = blockIdx.x * 32, t = threadIdx.x;

    // --- stage K window (160 rows, zero-padded) ---
    const float* Kb = g_K + (size_t)b * SEQ * DQ;
    for (int idx = t; idx < KROWS * 16; idx += 256) {
        int r = idx >> 4, c4 = idx & 15;
        int j = n0 - 64 + r;
        float4 v = (j >= 0 && j < SEQ) ? *(const float4*)(Kb + (size_t)j * DQ + c4 * 4)
                                       : make_float4(0.f, 0.f, 0.f, 0.f);
        *(float4*)(Ks + r * AP + c4 * 4) = v;
    }
    // --- stage Q tile ---
    const float* Qb = g_Q + ((size_t)b * SEQ + n0) * DQ;
    for (int idx = t; idx < 32 * 16; idx += 256) {
        int r = idx >> 4, c4 = idx & 15;
        *(float4*)(Qs + r * AP + c4 * 4) = *(const float4*)(Qb + (size_t)r * DQ + c4 * 4);
    }
    // --- stage V transposed: Vst[d][c] = Vc[c][d]; zero-pad c=129..131 ---
    for (int idx = t; idx < NC * 16; idx += 256) {
        int r = idx >> 4, c4 = idx & 15;     // r = c index, c4*4.. = d
        float4 v = *(const float4*)(g_Vc + ((size_t)b * NC + r) * DQ + c4 * 4);
        Vst[(c4 * 4 + 0) * EP + r] = v.x;
        Vst[(c4 * 4 + 1) * EP + r] = v.y;
        Vst[(c4 * 4 + 2) * EP + r] = v.z;
        Vst[(c4 * 4 + 3) * EP + r] = v.w;
    }
    if (t < DQ) {
        Vst[t * EP + 129] = 0.f;
        Vst[t * EP + 130] = 0.f;
        Vst[t * EP + 131] = 0.f;
        float s = ZCONST * bv[t];
#pragma unroll
        for (int kg = 0; kg < 8; kg++) s += g_vtp[(b * 8 + kg) * DQ + t];
        Vt[t] = s;
    }
    __syncthreads();

    const int lane = t & 31, w = t >> 5;
    const int lr = lane & 7, lc = lane >> 3;   // lane-adjacent row / col index
    const int rw = w & 1,  cw = w >> 1;        // warp: row-half x col-quarter

    // --- phase 1: S(32x160) = Q * Ks^T.  thread: rows rw*16+lr+{0,8},
    //     cols cw*40+lc+4j (j=0..9).  LDS.128 k-quads, FFMA2. ---
    ull acc2[2][10];
#pragma unroll
    for (int i = 0; i < 2; i++)
#pragma unroll
        for (int j = 0; j < 10; j++) acc2[i][j] = 0ull;

    const int r0 = rw * 16 + lr;
    const int c0 = cw * 40 + lc;

#pragma unroll 4
    for (int kq = 0; kq < 16; kq++) {
        float4 qv0 = *(const float4*)(Qs + r0 * AP + kq * 4);
        float4 qv1 = *(const float4*)(Qs + (r0 + 8) * AP + kq * 4);
        ull q0a = pack2(qv0.x, qv0.y), q0b = pack2(qv0.z, qv0.w);
        ull q1a = pack2(qv1.x, qv1.y), q1b = pack2(qv1.z, qv1.w);
#pragma unroll
        for (int j = 0; j < 10; j++) {
            float4 kv = *(const float4*)(Ks + (c0 + 4 * j) * AP + kq * 4);
            ull ka = pack2(kv.x, kv.y), kb = pack2(kv.z, kv.w);
            ffma2(acc2[0][j], q0a, ka);
            ffma2(acc2[0][j], q0b, kb);
            ffma2(acc2[1][j], q1a, ka);
            ffma2(acc2[1][j], q1b, kb);
        }
    }
    __syncthreads();   // all Ks reads done before Es overlay writes

    // --- phase 1.5: exp + scatter into Es[row][c], c = cc - row ---
#pragma unroll
    for (int i = 0; i < 2; i++) {
        int np = r0 + 8 * i;
#pragma unroll
        for (int j = 0; j < 10; j++) {
            int cc = c0 + 4 * j;
            int c = cc - np;
            if (c >= 0 && c < NC)
                Es[np * EP + c] = expf(lo32(acc2[i][j]) + hi32(acc2[i][j]));
        }
    }
    if (t < 32) {
        Es[t * EP + 129] = 0.f;
        Es[t * EP + 130] = 0.f;
        Es[t * EP + 131] = 0.f;
    }
    __syncthreads();

    // --- Z per row: 8 warps x 4 rows ---
    {
#pragma unroll
        for (int rr = 0; rr < 4; rr++) {
            int r = w * 4 + rr;
            float s = Es[r * EP + lane] + Es[r * EP + lane + 32]
                    + Es[r * EP + lane + 64] + Es[r * EP + lane + 96];
            if (lane == 0) s += Es[r * EP + 128];
#pragma unroll
            for (int o = 16; o > 0; o >>= 1) s += __shfl_xor_sync(0xffffffffu, s, o);
            if (lane == 0) Zi[r] = 1.0f / (s + ZCONST);
        }
    }
    __syncthreads();

    // --- phase 2: O(32x64) = E * V^T.  thread: rows rw*16+lr+{0,8},
    //     d = dw*16+ld+4j (j=0..3).  LDS.128 c-quads, FFMA2. ---
    const int ld = lc;            // same lane split
    const int rw2 = rw, dw = cw;  // same warp split
    const int d0 = dw * 16 + ld;
    const int rr0 = rw2 * 16 + lr;

    ull oacc2[2][4];
#pragma unroll
    for (int i = 0; i < 2; i++)
#pragma unroll
        for (int j = 0; j < 4; j++) oacc2[i][j] = 0ull;

#pragma unroll 3
    for (int q = 0; q < 33; q++) {
        float4 ev0 = *(const float4*)(Es + rr0 * EP + q * 4);
        float4 ev1 = *(const float4*)(Es + (rr0 + 8) * EP + q * 4);
        ull e0a = pack2(ev0.x, ev0.y), e0b = pack2(ev0.z, ev0.w);
        ull e1a = pack2(ev1.x, ev1.y), e1b = pack2(ev1.z, ev1.w);
#pragma unroll
        for (int j = 0; j < 4; j++) {
            float4 vv = *(const float4*)(Vst + (d0 + 4 * j) * EP + q * 4);
            ull va = pack2(vv.x, vv.y), vb = pack2(vv.z, vv.w);
            ffma2(oacc2[0][j], e0a, va);
            ffma2(oacc2[0][j], e0b, vb);
            ffma2(oacc2[1][j], e1a, va);
            ffma2(oacc2[1][j], e1b, vb);
        }
    }

#pragma unroll
    for (int i = 0; i < 2; i++) {
        int np = rr0 + 8 * i;
        float zi = Zi[np];
#pragma unroll
        for (int j = 0; j < 4; j++) {
            int d = d0 + 4 * j;
            out[((size_t)b * SEQ + n0 + np) * DQ + d] =
                (lo32(oacc2[i][j]) + hi32(oacc2[i][j]) + Vt[d]) * zi;
        }
    }
}

// ============================================================
// launcher
// ============================================================
extern "C" void kernel_launch(void* const* d_in, const int* in_sizes, int n_in,
                              void* d_out, int out_size) {
    const float* x  = (const float*)d_in[0];
    const float* Wq = (const float*)d_in[1];
    const float* bq = (const float*)d_in[2];
    const float* Wk = (const float*)d_in[3];
    const float* bk = (const float*)d_in[4];
    const float* Wv = (const float*)d_in[5];
    const float* bv = (const float*)d_in[6];
    float* out = (float*)d_out;

    cudaFuncSetAttribute(attn_kernel, cudaFuncAttributeMaxDynamicSharedMemorySize, A_BYTES);

    prep_kernel<<<514, 128>>>(x, Wq, Wk, Wv, bv);
    vtail_combine_kernel<<<dim3(8, BATCH), 256>>>(Wv);
    proj_qk_kernel<<<dim3(SEQ / 32, BATCH), 256>>>(x, bq, bk);
    attn_kernel<<<dim3(SEQ / 32, BATCH), 256, A_BYTES>>>(out, bv);
}